// round 1
// baseline (speedup 1.0000x reference)
#include <cuda_runtime.h>

// Fused curve-LUT apply:
//   out[b,c,h,w] = tanh( sum_i trilinear( param[b, c*24 + i*8 + z, yc, xc],
//                                          ix(w), iy(h), iz(x[b,i,h,w]) ) )
// Control grid: 256x256 x 8 depth, align_corners=True, border clamp.
// Strategy: one CTA per 32x32 pixel tile; stage the <=10x10 control patch
// (all 72 planes, 28.8KB) into shared in point-major [i][dy][dx][z*3+c]
// layout (point stride padded to 25 floats -> bank-conflict-friendly),
// then each pixel reads only the 6 floats per corner it needs.

#define TW 32
#define TH 32
#define XS 10
#define YS 10
#define PT 25           // padded floats per control point (24 used)
#define NTHREADS 256

__device__ __forceinline__ float fast_tanh(float v) {
    float y;
    asm("tanh.approx.f32 %0, %1;" : "=f"(y) : "f"(v));
    return y;
}

__global__ __launch_bounds__(NTHREADS)
void curve_apply_kernel(const float* __restrict__ x,
                        const float* __restrict__ param,
                        float* __restrict__ out)
{
    __shared__ float sh[3 * YS * XS * PT];   // 7500 floats = 30 KB

    const int b  = blockIdx.z;
    const int w0 = blockIdx.x * TW;
    const int h0 = blockIdx.y * TH;
    const float r = 255.0f / 1023.0f;        // ix = w * 255/1023 (align_corners)
    const int xbase = (int)floorf((float)w0 * r);
    const int ybase = (int)floorf((float)h0 * r);
    const int tid = threadIdx.x;

    // ---- Stage control-point patch into shared (transpose on the fly) ----
    // Source plane index p = c*24 + i*8 + z  (param is [B,72,256,256]).
    const float* prm = param + (size_t)b * 72 * 65536;
    #pragma unroll 1
    for (int idx = tid; idx < 72 * YS * XS; idx += NTHREADS) {
        int plane = idx / (YS * XS);
        int pos   = idx - plane * (YS * XS);
        int dy = pos / XS;
        int dx = pos - dy * XS;
        int yy = min(ybase + dy, 255);
        int xx = min(xbase + dx, 255);
        float v = __ldg(prm + plane * 65536 + yy * 256 + xx);
        int c  = plane / 24;
        int rm = plane - c * 24;
        int i  = rm >> 3;
        int z  = rm & 7;
        sh[((i * YS + dy) * XS + dx) * PT + z * 3 + c] = v;
    }
    __syncthreads();

    // ---- Pixel loop: 8 warps x 32 lanes, 4 rows per thread ----
    const int lane = tid & 31;
    const int rowi = tid >> 5;
    const int w = w0 + lane;

    float ixf = fminf((float)w * r, 255.0f);
    float x0f = floorf(ixf);
    float wx  = ixf - x0f;
    int   x0  = (int)x0f;
    int   dx0 = x0 - xbase;
    int   dx1 = min(x0 + 1, 255) - xbase;

    const float* xb = x   + (size_t)b * 3 * 1048576;
    float*       ob = out + (size_t)b * 3 * 1048576;

    #pragma unroll
    for (int k = 0; k < 4; k++) {
        int h = h0 + rowi + 8 * k;
        float iyf = fminf((float)h * r, 255.0f);
        float y0f = floorf(iyf);
        float wy  = iyf - y0f;
        int   y0  = (int)y0f;
        int   dy0 = y0 - ybase;
        int   dy1 = min(y0 + 1, 255) - ybase;

        int cb00 = (dy0 * XS + dx0) * PT;
        int cb01 = (dy0 * XS + dx1) * PT;
        int cb10 = (dy1 * XS + dx0) * PT;
        int cb11 = (dy1 * XS + dx1) * PT;

        float w11 = wy * wx;
        float w10 = wy - w11;
        float w01 = wx - w11;
        float w00 = 1.0f - wy - wx + w11;

        int pix = h * 1024 + w;
        float acc0 = 0.f, acc1 = 0.f, acc2 = 0.f;

        #pragma unroll
        for (int i = 0; i < 3; i++) {
            float gz  = __ldg(xb + (size_t)i * 1048576 + pix);
            float izf = fminf(fmaxf(gz * 3.5f + 3.5f, 0.0f), 7.0f);
            float z0f = floorf(izf);
            float wz  = izf - z0f;
            int   z0  = (int)z0f;
            int   o0  = z0 * 3;
            int   o1  = min(z0 + 1, 7) * 3;
            const float* shi = sh + i * (YS * XS * PT);

            #define CORNER(CB, WC)                                          \
            {                                                               \
                const float* p = shi + (CB);                                \
                float a0 = p[o0],     a1 = p[o0 + 1], a2 = p[o0 + 2];       \
                float b0 = p[o1],     b1 = p[o1 + 1], b2 = p[o1 + 2];       \
                acc0 += (WC) * (a0 + wz * (b0 - a0));                       \
                acc1 += (WC) * (a1 + wz * (b1 - a1));                       \
                acc2 += (WC) * (a2 + wz * (b2 - a2));                       \
            }
            CORNER(cb00, w00)
            CORNER(cb01, w01)
            CORNER(cb10, w10)
            CORNER(cb11, w11)
            #undef CORNER
        }

        ob[pix]               = fast_tanh(acc0);
        ob[1048576 + pix]     = fast_tanh(acc1);
        ob[2 * 1048576 + pix] = fast_tanh(acc2);
    }
}

extern "C" void kernel_launch(void* const* d_in, const int* in_sizes, int n_in,
                              void* d_out, int out_size)
{
    const float* x     = (const float*)d_in[0];   // [4,3,1024,1024] fp32
    const float* param = (const float*)d_in[1];   // [4,72,256,256]  fp32
    float*       out   = (float*)d_out;           // [4,3,1024,1024] fp32

    dim3 grid(1024 / TW, 1024 / TH, 4);
    curve_apply_kernel<<<grid, NTHREADS>>>(x, param, out);
}